// round 15
// baseline (speedup 1.0000x reference)
#include <cuda_runtime.h>
#include <cstdint>

#define NN 50000
#define NE 800000
#define FIN 8          // concat(x[6], pos[2])
#define HID 64
#define NOUT 10
#define P16 16         // padded layer-3 feature width
#define NK 4           // K+1 weight slices
#define NSCANB 196     // ceil(NN/256)
#define RDY (1 << 30)  // scan aggregate ready flag (NE < 2^20)

typedef unsigned long long ull;

// ---------------- scratch (no allocation allowed) ----------------
struct Scratch {
    alignas(128) ull   pk[NN];            // packed (cnt<<40 | fixed-point deg)
    alignas(128) float dinv[NN];
    alignas(128) int   rowptr[NN + 1];
    alignas(128) int   cursor[NN];
    alignas(128) int   bsum[256];
    alignas(128) int2  edg[NE];           // (src, bitcast(norm))
    alignas(128) float h0 [NN * FIN];
    alignas(128) float t8a[NN * FIN];
    alignas(128) float t8b[NN * FIN];
    alignas(128) float t8c[NN * FIN];
    alignas(128) float hA[NN * HID];
    alignas(128) float hB[NN * HID];
    alignas(128) float hC[NN * HID];
    alignas(128) float hD[NN * HID];
    alignas(128) float g0[NN * P16];
    alignas(128) float g1[NN * P16];
    alignas(128) float g2[NN * P16];
    alignas(128) float g3[NN * P16];
    alignas(128) float p16a[NN * P16];
    alignas(128) float p16b[NN * P16];
};
__device__ Scratch g_s;

// ---------------- f32x2 packed helpers ----------------
__device__ __forceinline__ ull dup2(float v) {
    ull r; unsigned int b = __float_as_uint(v);
    asm("mov.b64 %0, {%1, %1};" : "=l"(r) : "r"(b));
    return r;
}
__device__ __forceinline__ void fma2(ull& d, ull a, ull b) {
    asm("fma.rn.f32x2 %0, %1, %2, %0;" : "+l"(d) : "l"(a), "l"(b));
}
__device__ __forceinline__ ull add2(ull a, ull b) {
    ull r;
    asm("add.rn.f32x2 %0, %1, %2;" : "=l"(r) : "l"(a), "l"(b));
    return r;
}
__device__ __forceinline__ float2 unpack2(ull v) {
    float2 u;
    asm("mov.b64 {%0, %1}, %2;" : "=f"(u.x), "=f"(u.y) : "l"(v));
    return u;
}

// per-block int64 detection: odd 32-bit words all zero <=> int64 (indices < 50000)
__device__ __forceinline__ int detect_is64_block(const int* __restrict__ ei32) {
    int t = threadIdx.x;
    int samp = 0;
    if (t < 64) {
        long long idx = 2LL * ((long long)t * (NE / 64)) + 1;
        samp = (ei32[idx] != 0);
    }
    int any = __syncthreads_or(samp);
    return !any;
}

__device__ __forceinline__ int load_src(const int* ei32, int e, int is64) {
    int v = is64 ? ei32[2 * e] : ei32[e];
    return min(max(v, 0), NN - 1);
}
__device__ __forceinline__ int load_dst(const int* ei32, int e, int is64) {
    long long base = is64 ? 2LL * ((long long)NE + e) : (long long)NE + e;
    int v = ei32[base];
    return min(max(v, 0), NN - 1);
}

// ---------------- graph preprocessing ----------------
__global__ void k_zero_concat(const float* __restrict__ x, const float* __restrict__ pos,
                              float* __restrict__ h0,
                              ull* __restrict__ pk, int* __restrict__ bsum) {
    int i = blockIdx.x * blockDim.x + threadIdx.x;
    if (blockIdx.x == 0) bsum[threadIdx.x] = 0;
    if (i >= NN) return;
    pk[i] = 0ULL;
    float* o = h0 + i * FIN;
    const float* xi = x + i * 6;
    o[0] = xi[0]; o[1] = xi[1]; o[2] = xi[2];
    o[3] = xi[3]; o[4] = xi[4]; o[5] = xi[5];
    o[6] = pos[i * 2 + 0];
    o[7] = pos[i * 2 + 1];
}

// 4 edges/thread, 4 independent atomic chains; one packed atomic per edge
__global__ void k_deg_cnt(const int* __restrict__ ei32,
                          const float* __restrict__ ea, ull* __restrict__ pk) {
    int is64 = detect_is64_block(ei32);
    int e = (blockIdx.x * blockDim.x + threadIdx.x) * 4;
    if (e >= NE) return;
    int d0 = load_dst(ei32, e + 0, is64);
    int d1 = load_dst(ei32, e + 1, is64);
    int d2 = load_dst(ei32, e + 2, is64);
    int d3 = load_dst(ei32, e + 3, is64);
    float4 eav = *(const float4*)(ea + e);
    atomicAdd(&pk[d0], (1ULL << 40) | (ull)(eav.x * 1073741824.0f));
    atomicAdd(&pk[d1], (1ULL << 40) | (ull)(eav.y * 1073741824.0f));
    atomicAdd(&pk[d2], (1ULL << 40) | (ull)(eav.z * 1073741824.0f));
    atomicAdd(&pk[d3], (1ULL << 40) | (ull)(eav.w * 1073741824.0f));
}

// fused scan: block-local scan + decoupled lookback (all 196 blocks co-resident)
__global__ void k_scan(const ull* __restrict__ pk,
                       int* __restrict__ rowptr, int* __restrict__ cursor,
                       float* __restrict__ dinv, int* __restrict__ bsum) {
    int i = blockIdx.x * 256 + threadIdx.x;
    int lane = threadIdx.x & 31, wid = threadIdx.x >> 5;
    ull pkv = (i < NN) ? pk[i] : 0ULL;
    int v = (int)(pkv >> 40);
    int x = v;
    #pragma unroll
    for (int o = 1; o < 32; o <<= 1) {
        int n = __shfl_up_sync(0xFFFFFFFFu, x, o);
        if (lane >= o) x += n;
    }
    __shared__ int ws[8];
    __shared__ int s_base;
    if (lane == 31) ws[wid] = x;
    __syncthreads();
    if (threadIdx.x < 8) {
        int w = ws[threadIdx.x];
        #pragma unroll
        for (int o = 1; o < 8; o <<= 1) {
            int n = __shfl_up_sync(0xFFu, w, o);
            if ((threadIdx.x & 7) >= o) w += n;
        }
        ws[threadIdx.x] = w;
    }
    __syncthreads();
    int excl = x - v + (wid > 0 ? ws[wid - 1] : 0);
    int btotal = ws[7];

    if (threadIdx.x == 255) atomicExch(&bsum[blockIdx.x], btotal | RDY);
    if (threadIdx.x < 32) {
        int acc = 0;
        for (int base = 0; base < (int)blockIdx.x; base += 32) {
            int j = base + lane;
            int val = 0;
            if (j < (int)blockIdx.x) {
                do { val = ((volatile int*)bsum)[j]; } while (!(val & RDY));
                val &= ~RDY;
            }
            #pragma unroll
            for (int o = 16; o >= 1; o >>= 1)
                val += __shfl_xor_sync(0xFFFFFFFFu, val, o);
            acc += val;
        }
        if (threadIdx.x == 0) s_base = acc;
    }
    __syncthreads();

    if (i >= NN) return;
    int r = excl + s_base;
    rowptr[i] = r;
    cursor[i] = r;
    double dv = (double)(pkv & ((1ULL << 40) - 1)) * (1.0 / 1073741824.0);
    float d = (float)dv;
    dinv[i] = (d > 0.0f) ? rsqrtf(d) : 0.0f;
    if (i == 0) rowptr[NN] = NE;
}

// 4 edges/thread, independent gather/atomic/scatter chains
__global__ void k_fill(const int* __restrict__ ei32,
                       const float* __restrict__ ea,
                       const float* __restrict__ dinv,
                       int* __restrict__ cursor, int2* __restrict__ edg) {
    int is64 = detect_is64_block(ei32);
    int e = (blockIdx.x * blockDim.x + threadIdx.x) * 4;
    if (e >= NE) return;
    int s0 = load_src(ei32, e + 0, is64), d0 = load_dst(ei32, e + 0, is64);
    int s1 = load_src(ei32, e + 1, is64), d1 = load_dst(ei32, e + 1, is64);
    int s2 = load_src(ei32, e + 2, is64), d2 = load_dst(ei32, e + 2, is64);
    int s3 = load_src(ei32, e + 3, is64), d3 = load_dst(ei32, e + 3, is64);
    float4 eav = *(const float4*)(ea + e);
    float ds0 = dinv[s0], ds1 = dinv[s1], ds2 = dinv[s2], ds3 = dinv[s3];
    float dd0 = dinv[d0], dd1 = dinv[d1], dd2 = dinv[d2], dd3 = dinv[d3];
    float n0 = ds0 * eav.x * dd0;
    float n1 = ds1 * eav.y * dd1;
    float n2 = ds2 * eav.z * dd2;
    float n3 = ds3 * eav.w * dd3;
    int p0 = atomicAdd(&cursor[d0], 1);
    int p1 = atomicAdd(&cursor[d1], 1);
    int p2 = atomicAdd(&cursor[d2], 1);
    int p3 = atomicAdd(&cursor[d3], 1);
    edg[p0] = make_int2(s0, __float_as_int(n0));
    edg[p1] = make_int2(s1, __float_as_int(n1));
    edg[p2] = make_int2(s2, __float_as_int(n2));
    edg[p3] = make_int2(s3, __float_as_int(n3));
}

// ---------------- propagate (CSR gather; 4-deep pipeline; exact-size grids) ---
template<int W>
__global__ void k_propW(const float* __restrict__ h, const float* __restrict__ add,
                        float* __restrict__ o,
                        const int* __restrict__ rowptr, const int2* __restrict__ edg) {
    const int GPW = 32 / W;
    int warp = blockIdx.x * (blockDim.x >> 5) + (threadIdx.x >> 5);
    int lane = threadIdx.x & 31;
    int node = warp * GPW + lane / W;
    int f = lane % W;
    if (node >= NN) return;
    int b = rowptr[node], e = rowptr[node + 1];
    float a0 = add ? add[node * W + f] : 0.0f;
    float a1 = 0.0f, a2 = 0.0f, a3 = 0.0f;
    int i = b;
    for (; i + 4 <= e; i += 4) {
        int2 e0 = edg[i], e1 = edg[i + 1], e2 = edg[i + 2], e3 = edg[i + 3];
        float h0v = h[e0.x * W + f];
        float h1v = h[e1.x * W + f];
        float h2v = h[e2.x * W + f];
        float h3v = h[e3.x * W + f];
        a0 += __int_as_float(e0.y) * h0v;
        a1 += __int_as_float(e1.y) * h1v;
        a2 += __int_as_float(e2.y) * h2v;
        a3 += __int_as_float(e3.y) * h3v;
    }
    for (; i < e; i++) {
        int2 ev = edg[i];
        a0 += __int_as_float(ev.y) * h[ev.x * W + f];
    }
    o[node * W + f] = (a0 + a1) + (a2 + a3);
}

// warp per node; lane f covers features {2f, 2f+1}; 4 independent gather chains
__global__ void k_prop64(const ull* __restrict__ h, ull* __restrict__ o,
                         const int* __restrict__ rowptr, const int2* __restrict__ edg) {
    int node = blockIdx.x * (blockDim.x >> 5) + (threadIdx.x >> 5);
    int lane = threadIdx.x & 31;
    if (node >= NN) return;
    int b = rowptr[node], e = rowptr[node + 1];
    ull a0 = 0, a1 = 0, a2 = 0, a3 = 0;
    int i = b;
    for (; i + 4 <= e; i += 4) {
        int2 e0 = edg[i], e1 = edg[i + 1], e2 = edg[i + 2], e3 = edg[i + 3];
        ull h0v = h[e0.x * 32 + lane];
        ull h1v = h[e1.x * 32 + lane];
        ull h2v = h[e2.x * 32 + lane];
        ull h3v = h[e3.x * 32 + lane];
        fma2(a0, h0v, dup2(__int_as_float(e0.y)));
        fma2(a1, h1v, dup2(__int_as_float(e1.y)));
        fma2(a2, h2v, dup2(__int_as_float(e2.y)));
        fma2(a3, h3v, dup2(__int_as_float(e3.y)));
    }
    for (; i < e; i++) {
        int2 ev = edg[i];
        fma2(a0, h[ev.x * 32 + lane], dup2(__int_as_float(ev.y)));
    }
    o[node * 32 + lane] = add2(add2(a0, a1), add2(a2, a3));
}

// final Horner propagate + log_softmax via width-16 shuffle reduction
__global__ void k_prop16_lsm(const float* __restrict__ h, const float* __restrict__ add,
                             float* __restrict__ outp,
                             const int* __restrict__ rowptr, const int2* __restrict__ edg) {
    int warp = blockIdx.x * (blockDim.x >> 5) + (threadIdx.x >> 5);
    int lane = threadIdx.x & 31;
    int node = warp * 2 + (lane >> 4);
    int f = lane & 15;
    if (node >= NN) return;
    int b = rowptr[node], e = rowptr[node + 1];
    float a0 = add[node * P16 + f], a1 = 0.0f, a2 = 0.0f, a3 = 0.0f;
    int i = b;
    for (; i + 4 <= e; i += 4) {
        int2 e0 = edg[i], e1 = edg[i + 1], e2 = edg[i + 2], e3 = edg[i + 3];
        float h0v = h[e0.x * P16 + f];
        float h1v = h[e1.x * P16 + f];
        float h2v = h[e2.x * P16 + f];
        float h3v = h[e3.x * P16 + f];
        a0 += __int_as_float(e0.y) * h0v;
        a1 += __int_as_float(e1.y) * h1v;
        a2 += __int_as_float(e2.y) * h2v;
        a3 += __int_as_float(e3.y) * h3v;
    }
    for (; i < e; i++) {
        int2 ev = edg[i];
        a0 += __int_as_float(ev.y) * h[ev.x * P16 + f];
    }
    float acc = (a0 + a1) + (a2 + a3);
    float mv = (f < NOUT) ? acc : -1e30f;
    #pragma unroll
    for (int o = 8; o >= 1; o >>= 1)
        mv = fmaxf(mv, __shfl_xor_sync(0xFFFFFFFFu, mv, o, 16));
    float ex = (f < NOUT) ? expf(acc - mv) : 0.0f;
    float s = ex;
    #pragma unroll
    for (int o = 8; o >= 1; o >>= 1)
        s += __shfl_xor_sync(0xFFFFFFFFu, s, o, 16);
    float l = mv + logf(s);
    if (f < NOUT) outp[node * NOUT + f] = acc - l;
}

// ---------------- fused layer GEMMs (packed f32x2 FMA) ----------------
__global__ void k_gemm_l1(const float* __restrict__ h0, const float* __restrict__ h1,
                          const float* __restrict__ h2, const float* __restrict__ h3,
                          const float* __restrict__ W, const float* __restrict__ bias,
                          float* __restrict__ outp) {
    __shared__ alignas(16) float sW[NK * FIN * HID];
    __shared__ alignas(16) float sb[HID];
    for (int i = threadIdx.x; i < NK * FIN * HID; i += blockDim.x) sW[i] = W[i];
    if (threadIdx.x < HID) sb[threadIdx.x] = bias[threadIdx.x];
    __syncthreads();

    int row = blockIdx.x * blockDim.x + threadIdx.x;
    if (row >= NN) return;
    const float* hs[NK] = {h0 + row * FIN, h1 + row * FIN, h2 + row * FIN, h3 + row * FIN};

    ull acc2[HID / 2];
    const ull* sb64 = (const ull*)sb;
    #pragma unroll
    for (int c = 0; c < HID / 2; c++) acc2[c] = sb64[c];

    #pragma unroll
    for (int kk = 0; kk < NK; kk++) {
        const float4* hp = (const float4*)hs[kk];
        float4 h04 = hp[0], h14 = hp[1];
        float hv[FIN] = {h04.x, h04.y, h04.z, h04.w, h14.x, h14.y, h14.z, h14.w};
        #pragma unroll
        for (int k = 0; k < FIN; k++) {
            ull hd = dup2(hv[k]);
            const ulonglong2* w2 = (const ulonglong2*)(sW + (kk * FIN + k) * HID);
            #pragma unroll
            for (int c = 0; c < HID / 4; c++) {
                ulonglong2 wp = w2[c];
                fma2(acc2[2 * c], wp.x, hd);
                fma2(acc2[2 * c + 1], wp.y, hd);
            }
        }
    }
    float4* op = (float4*)(outp + row * HID);
    #pragma unroll
    for (int c = 0; c < HID / 4; c++) {
        float2 u0 = unpack2(acc2[2 * c]), u1 = unpack2(acc2[2 * c + 1]);
        op[c] = make_float4(fmaxf(u0.x, 0.f), fmaxf(u0.y, 0.f),
                            fmaxf(u1.x, 0.f), fmaxf(u1.y, 0.f));
    }
}

__global__ void k_gemm_l2(const float* __restrict__ h0, const float* __restrict__ h1,
                          const float* __restrict__ h2, const float* __restrict__ h3,
                          const float* __restrict__ W, const float* __restrict__ bias,
                          float* __restrict__ outp) {
    extern __shared__ float sW[];          // 64KB
    __shared__ alignas(16) float sb[HID];
    for (int i = threadIdx.x; i < NK * HID * HID; i += blockDim.x) sW[i] = W[i];
    if (threadIdx.x < HID) sb[threadIdx.x] = bias[threadIdx.x];
    __syncthreads();

    int row = blockIdx.x * blockDim.x + threadIdx.x;
    if (row >= NN) return;
    const float* hs[NK] = {h0 + row * HID, h1 + row * HID, h2 + row * HID, h3 + row * HID};

    ull acc2[HID / 2];
    const ull* sb64 = (const ull*)sb;
    #pragma unroll
    for (int c = 0; c < HID / 2; c++) acc2[c] = sb64[c];

    for (int kk = 0; kk < NK; kk++) {
        const float4* hp = (const float4*)hs[kk];
        #pragma unroll 4
        for (int k4 = 0; k4 < HID / 4; k4++) {
            float4 hv = hp[k4];
            float hvv[4] = {hv.x, hv.y, hv.z, hv.w};
            #pragma unroll
            for (int j = 0; j < 4; j++) {
                ull hd = dup2(hvv[j]);
                const ulonglong2* w2 =
                    (const ulonglong2*)(sW + (kk * HID + k4 * 4 + j) * HID);
                #pragma unroll
                for (int c = 0; c < HID / 4; c++) {
                    ulonglong2 wp = w2[c];
                    fma2(acc2[2 * c], wp.x, hd);
                    fma2(acc2[2 * c + 1], wp.y, hd);
                }
            }
        }
    }
    float4* op = (float4*)(outp + row * HID);
    #pragma unroll
    for (int c = 0; c < HID / 4; c++) {
        float2 u0 = unpack2(acc2[2 * c]), u1 = unpack2(acc2[2 * c + 1]);
        op[c] = make_float4(fmaxf(u0.x, 0.f), fmaxf(u0.y, 0.f),
                            fmaxf(u1.x, 0.f), fmaxf(u1.y, 0.f));
    }
}

// layer-3 transforms: g_k = h @ W3[k] (bias folded into g0); pad to 16
__global__ void k_tx3(const float* __restrict__ h, const float* __restrict__ W,
                      const float* __restrict__ bias,
                      float* __restrict__ g0, float* __restrict__ g1,
                      float* __restrict__ g2, float* __restrict__ g3) {
    __shared__ float sW[NK * HID * NOUT];
    __shared__ float sb[NOUT];
    for (int i = threadIdx.x; i < NK * HID * NOUT; i += blockDim.x) sW[i] = W[i];
    if (threadIdx.x < NOUT) sb[threadIdx.x] = bias[threadIdx.x];
    __syncthreads();

    int row = blockIdx.x * blockDim.x + threadIdx.x;
    if (row >= NN) return;
    const float4* hp = (const float4*)(h + row * HID);

    float acc[NK * NOUT];
    #pragma unroll
    for (int kk = 0; kk < NK; kk++)
        #pragma unroll
        for (int c = 0; c < NOUT; c++)
            acc[kk * NOUT + c] = (kk == 0) ? sb[c] : 0.0f;

    for (int k4 = 0; k4 < HID / 4; k4++) {
        float4 hv = hp[k4];
        #pragma unroll
        for (int kk = 0; kk < NK; kk++) {
            const float* w = sW + kk * HID * NOUT + (k4 * 4) * NOUT;
            #pragma unroll
            for (int c = 0; c < NOUT; c++) acc[kk * NOUT + c] += hv.x * w[c];
            #pragma unroll
            for (int c = 0; c < NOUT; c++) acc[kk * NOUT + c] += hv.y * w[NOUT + c];
            #pragma unroll
            for (int c = 0; c < NOUT; c++) acc[kk * NOUT + c] += hv.z * w[2 * NOUT + c];
            #pragma unroll
            for (int c = 0; c < NOUT; c++) acc[kk * NOUT + c] += hv.w * w[3 * NOUT + c];
        }
    }
    float* gs[NK] = {g0 + row * P16, g1 + row * P16, g2 + row * P16, g3 + row * P16};
    #pragma unroll
    for (int kk = 0; kk < NK; kk++) {
        #pragma unroll
        for (int c = 0; c < NOUT; c++) gs[kk][c] = acc[kk * NOUT + c];
        #pragma unroll
        for (int c = NOUT; c < P16; c++) gs[kk][c] = 0.0f;
    }
}

// ---------------- launch ----------------
extern "C" void kernel_launch(void* const* d_in, const int* in_sizes, int n_in,
                              void* d_out, int out_size) {
    const float *x = 0, *pos = 0, *ea = 0, *W1 = 0, *b1 = 0, *W2 = 0, *b2 = 0,
                *W3 = 0, *b3 = 0;
    const int* ei32 = 0;
    for (int i = 0; i < n_in; i++) {
        switch (in_sizes[i]) {
            case 1600000: ei32 = (const int*)d_in[i]; break;
            case  800000: ea  = (const float*)d_in[i]; break;
            case  300000: x   = (const float*)d_in[i]; break;
            case  100000: pos = (const float*)d_in[i]; break;
            case    2048: W1  = (const float*)d_in[i]; break;
            case   16384: W2  = (const float*)d_in[i]; break;
            case    2560: W3  = (const float*)d_in[i]; break;
            case      10: b3  = (const float*)d_in[i]; break;
            case      64:
                if (!b1) b1 = (const float*)d_in[i];
                else     b2 = (const float*)d_in[i];
                break;
            default: break;
        }
    }
    float* out = (float*)d_out;

    Scratch* S;
    cudaGetSymbolAddress((void**)&S, g_s);
    cudaFuncSetAttribute(k_gemm_l2, cudaFuncAttributeMaxDynamicSharedMemorySize,
                         NK * HID * HID * (int)sizeof(float));

    const int BE4 = (NE / 4 + 255) / 256;   // 4 edges per thread
    const int BG = (NN + 127) / 128;
    const int BG2 = (NN + 255) / 256;
    const int BW = (NN + 7) / 8;
    const int B8  = (NN + 31) / 32;
    const int B16 = (NN + 15) / 16;

    k_zero_concat<<<NSCANB, 256>>>(x, pos, S->h0, S->pk, S->bsum);
    k_deg_cnt<<<BE4, 256>>>(ei32, ea, S->pk);
    k_scan<<<NSCANB, 256>>>((const ull*)S->pk, S->rowptr, S->cursor, S->dinv, S->bsum);
    k_fill<<<BE4, 256>>>(ei32, ea, (const float*)S->dinv, S->cursor, S->edg);

    // layer 1 (F=8 -> 64)
    k_propW<8><<<B8, 256>>>(S->h0,  nullptr, S->t8a, S->rowptr, S->edg);
    k_propW<8><<<B8, 256>>>(S->t8a, nullptr, S->t8b, S->rowptr, S->edg);
    k_propW<8><<<B8, 256>>>(S->t8b, nullptr, S->t8c, S->rowptr, S->edg);
    k_gemm_l1<<<BG, 128>>>(S->h0, S->t8a, S->t8b, S->t8c, W1, b1, S->hA);

    // layer 2 hops (fp32, 4-deep pipelined gathers, exact-size grids)
    k_prop64<<<BW, 256>>>((const ull*)S->hA, (ull*)S->hB, S->rowptr, S->edg);
    k_prop64<<<BW, 256>>>((const ull*)S->hB, (ull*)S->hC, S->rowptr, S->edg);
    k_prop64<<<BW, 256>>>((const ull*)S->hC, (ull*)S->hD, S->rowptr, S->edg);
    k_gemm_l2<<<BG2, 256, NK * HID * HID * (int)sizeof(float)>>>(
        S->hA, S->hB, S->hC, S->hD, W2, b2, S->hA);

    // layer 3 (64 -> 10): transform first, then Horner propagate at width 16
    k_tx3<<<BG, 128>>>(S->hA, W3, b3, S->g0, S->g1, S->g2, S->g3);
    k_propW<16><<<B16, 256>>>(S->g3,  S->g2, S->p16a, S->rowptr, S->edg);
    k_propW<16><<<B16, 256>>>(S->p16a, S->g1, S->p16b, S->rowptr, S->edg);
    k_prop16_lsm<<<B16, 256>>>(S->p16b, S->g0, out, S->rowptr, S->edg);
}

// round 16
// speedup vs baseline: 1.0158x; 1.0158x over previous
#include <cuda_runtime.h>
#include <cstdint>

#define NN 50000
#define NE 800000
#define FIN 8          // concat(x[6], pos[2])
#define HID 64
#define NOUT 10
#define P16 16         // padded layer-3 feature width
#define NK 4           // K+1 weight slices
#define NSCANB 196     // ceil(NN/256)
#define RDY (1 << 30)  // scan aggregate ready flag (NE < 2^20)

typedef unsigned long long ull;

// ---------------- scratch (no allocation allowed) ----------------
// pk and bsum are zero at every kernel_launch entry: zero-initialized at module
// load, and re-zeroed by k_prop16_lsm's tail each call (replay-safe invariant).
struct Scratch {
    alignas(128) ull   pk[NN];            // packed (cnt<<40 | fixed-point deg)
    alignas(128) float dinv[NN];
    alignas(128) int   rowptr[NN + 1];
    alignas(128) int   cursor[NN];
    alignas(128) int   bsum[256];
    alignas(128) int2  edg[NE];           // (src, bitcast(norm))
    alignas(128) float h0 [NN * FIN];
    alignas(128) float t8a[NN * FIN];
    alignas(128) float t8b[NN * FIN];
    alignas(128) float t8c[NN * FIN];
    alignas(128) float hA[NN * HID];
    alignas(128) float hB[NN * HID];
    alignas(128) float hC[NN * HID];
    alignas(128) float hD[NN * HID];
    alignas(128) float g0[NN * P16];
    alignas(128) float g1[NN * P16];
    alignas(128) float g2[NN * P16];
    alignas(128) float g3[NN * P16];
    alignas(128) float p16a[NN * P16];
    alignas(128) float p16b[NN * P16];
};
__device__ Scratch g_s;

// ---------------- f32x2 packed helpers ----------------
__device__ __forceinline__ ull dup2(float v) {
    ull r; unsigned int b = __float_as_uint(v);
    asm("mov.b64 %0, {%1, %1};" : "=l"(r) : "r"(b));
    return r;
}
__device__ __forceinline__ void fma2(ull& d, ull a, ull b) {
    asm("fma.rn.f32x2 %0, %1, %2, %0;" : "+l"(d) : "l"(a), "l"(b));
}
__device__ __forceinline__ ull add2(ull a, ull b) {
    ull r;
    asm("add.rn.f32x2 %0, %1, %2;" : "=l"(r) : "l"(a), "l"(b));
    return r;
}
__device__ __forceinline__ float2 unpack2(ull v) {
    float2 u;
    asm("mov.b64 {%0, %1}, %2;" : "=f"(u.x), "=f"(u.y) : "l"(v));
    return u;
}

// per-block int64 detection: odd 32-bit words all zero <=> int64 (indices < 50000)
__device__ __forceinline__ int detect_is64_block(const int* __restrict__ ei32) {
    int t = threadIdx.x;
    int samp = 0;
    if (t < 64) {
        long long idx = 2LL * ((long long)t * (NE / 64)) + 1;
        samp = (ei32[idx] != 0);
    }
    int any = __syncthreads_or(samp);
    return !any;
}

__device__ __forceinline__ int load_src(const int* ei32, int e, int is64) {
    int v = is64 ? ei32[2 * e] : ei32[e];
    return min(max(v, 0), NN - 1);
}
__device__ __forceinline__ int load_dst(const int* ei32, int e, int is64) {
    long long base = is64 ? 2LL * ((long long)NE + e) : (long long)NE + e;
    int v = ei32[base];
    return min(max(v, 0), NN - 1);
}

// ---------------- graph preprocessing ----------------
// deg/cnt accumulation (pk pre-zeroed invariant) + concat(x,pos) for node ids
__global__ void k_deg_cnt(const int* __restrict__ ei32,
                          const float* __restrict__ ea,
                          const float* __restrict__ x, const float* __restrict__ pos,
                          float* __restrict__ h0, ull* __restrict__ pk) {
    int is64 = detect_is64_block(ei32);
    int e = blockIdx.x * blockDim.x + threadIdx.x;
    if (e < NN) {                          // node-domain side work (first 196 blocks)
        float* o = h0 + e * FIN;
        const float* xi = x + e * 6;
        o[0] = xi[0]; o[1] = xi[1]; o[2] = xi[2];
        o[3] = xi[3]; o[4] = xi[4]; o[5] = xi[5];
        o[6] = pos[e * 2 + 0];
        o[7] = pos[e * 2 + 1];
    }
    if (e >= NE) return;
    int d = load_dst(ei32, e, is64);
    ull pv = (1ULL << 40) | (ull)(ea[e] * 1073741824.0f);
    atomicAdd(&pk[d], pv);
}

// fused scan: block-local scan + decoupled lookback (all 196 blocks co-resident)
__global__ void k_scan(const ull* __restrict__ pk,
                       int* __restrict__ rowptr, int* __restrict__ cursor,
                       float* __restrict__ dinv, int* __restrict__ bsum) {
    int i = blockIdx.x * 256 + threadIdx.x;
    int lane = threadIdx.x & 31, wid = threadIdx.x >> 5;
    ull pkv = (i < NN) ? pk[i] : 0ULL;
    int v = (int)(pkv >> 40);
    int x = v;
    #pragma unroll
    for (int o = 1; o < 32; o <<= 1) {
        int n = __shfl_up_sync(0xFFFFFFFFu, x, o);
        if (lane >= o) x += n;
    }
    __shared__ int ws[8];
    __shared__ int s_base;
    if (lane == 31) ws[wid] = x;
    __syncthreads();
    if (threadIdx.x < 8) {
        int w = ws[threadIdx.x];
        #pragma unroll
        for (int o = 1; o < 8; o <<= 1) {
            int n = __shfl_up_sync(0xFFu, w, o);
            if ((threadIdx.x & 7) >= o) w += n;
        }
        ws[threadIdx.x] = w;
    }
    __syncthreads();
    int excl = x - v + (wid > 0 ? ws[wid - 1] : 0);
    int btotal = ws[7];

    if (threadIdx.x == 255) atomicExch(&bsum[blockIdx.x], btotal | RDY);
    if (threadIdx.x < 32) {
        int acc = 0;
        for (int base = 0; base < (int)blockIdx.x; base += 32) {
            int j = base + lane;
            int val = 0;
            if (j < (int)blockIdx.x) {
                do { val = ((volatile int*)bsum)[j]; } while (!(val & RDY));
                val &= ~RDY;
            }
            #pragma unroll
            for (int o = 16; o >= 1; o >>= 1)
                val += __shfl_xor_sync(0xFFFFFFFFu, val, o);
            acc += val;
        }
        if (threadIdx.x == 0) s_base = acc;
    }
    __syncthreads();

    if (i >= NN) return;
    int r = excl + s_base;
    rowptr[i] = r;
    cursor[i] = r;
    double dv = (double)(pkv & ((1ULL << 40) - 1)) * (1.0 / 1073741824.0);
    float d = (float)dv;
    dinv[i] = (d > 0.0f) ? rsqrtf(d) : 0.0f;
    if (i == 0) rowptr[NN] = NE;
}

__global__ void k_fill(const int* __restrict__ ei32,
                       const float* __restrict__ ea,
                       const float* __restrict__ dinv,
                       int* __restrict__ cursor, int2* __restrict__ edg) {
    int is64 = detect_is64_block(ei32);
    int e = blockIdx.x * blockDim.x + threadIdx.x;
    if (e >= NE) return;
    int srcv = load_src(ei32, e, is64);
    int dstv = load_dst(ei32, e, is64);
    float nv = dinv[srcv] * ea[e] * dinv[dstv];
    int p = atomicAdd(&cursor[dstv], 1);
    edg[p] = make_int2(srcv, __float_as_int(nv));
}

// ---------------- propagate (CSR gather; 4-deep pipeline; exact-size grids) ---
template<int W>
__global__ void k_propW(const float* __restrict__ h, const float* __restrict__ add,
                        float* __restrict__ o,
                        const int* __restrict__ rowptr, const int2* __restrict__ edg) {
    const int GPW = 32 / W;
    int warp = blockIdx.x * (blockDim.x >> 5) + (threadIdx.x >> 5);
    int lane = threadIdx.x & 31;
    int node = warp * GPW + lane / W;
    int f = lane % W;
    if (node >= NN) return;
    int b = rowptr[node], e = rowptr[node + 1];
    float a0 = add ? add[node * W + f] : 0.0f;
    float a1 = 0.0f, a2 = 0.0f, a3 = 0.0f;
    int i = b;
    for (; i + 4 <= e; i += 4) {
        int2 e0 = edg[i], e1 = edg[i + 1], e2 = edg[i + 2], e3 = edg[i + 3];
        float h0v = h[e0.x * W + f];
        float h1v = h[e1.x * W + f];
        float h2v = h[e2.x * W + f];
        float h3v = h[e3.x * W + f];
        a0 += __int_as_float(e0.y) * h0v;
        a1 += __int_as_float(e1.y) * h1v;
        a2 += __int_as_float(e2.y) * h2v;
        a3 += __int_as_float(e3.y) * h3v;
    }
    for (; i < e; i++) {
        int2 ev = edg[i];
        a0 += __int_as_float(ev.y) * h[ev.x * W + f];
    }
    o[node * W + f] = (a0 + a1) + (a2 + a3);
}

// warp per node; lane f covers features {2f, 2f+1}; 4 independent gather chains
__global__ void k_prop64(const ull* __restrict__ h, ull* __restrict__ o,
                         const int* __restrict__ rowptr, const int2* __restrict__ edg) {
    int node = blockIdx.x * (blockDim.x >> 5) + (threadIdx.x >> 5);
    int lane = threadIdx.x & 31;
    if (node >= NN) return;
    int b = rowptr[node], e = rowptr[node + 1];
    ull a0 = 0, a1 = 0, a2 = 0, a3 = 0;
    int i = b;
    for (; i + 4 <= e; i += 4) {
        int2 e0 = edg[i], e1 = edg[i + 1], e2 = edg[i + 2], e3 = edg[i + 3];
        ull h0v = h[e0.x * 32 + lane];
        ull h1v = h[e1.x * 32 + lane];
        ull h2v = h[e2.x * 32 + lane];
        ull h3v = h[e3.x * 32 + lane];
        fma2(a0, h0v, dup2(__int_as_float(e0.y)));
        fma2(a1, h1v, dup2(__int_as_float(e1.y)));
        fma2(a2, h2v, dup2(__int_as_float(e2.y)));
        fma2(a3, h3v, dup2(__int_as_float(e3.y)));
    }
    for (; i < e; i++) {
        int2 ev = edg[i];
        fma2(a0, h[ev.x * 32 + lane], dup2(__int_as_float(ev.y)));
    }
    o[node * 32 + lane] = add2(add2(a0, a1), add2(a2, a3));
}

// final Horner propagate + log_softmax; tail re-zeroes pk/bsum for next replay
__global__ void k_prop16_lsm(const float* __restrict__ h, const float* __restrict__ add,
                             float* __restrict__ outp,
                             const int* __restrict__ rowptr, const int2* __restrict__ edg,
                             ull* __restrict__ pk, int* __restrict__ bsum) {
    if (blockIdx.x == 0) bsum[threadIdx.x] = 0;   // 256 threads cover bsum
    int warp = blockIdx.x * (blockDim.x >> 5) + (threadIdx.x >> 5);
    int lane = threadIdx.x & 31;
    int node = warp * 2 + (lane >> 4);
    int f = lane & 15;
    if (node >= NN) return;
    if (f == 0) pk[node] = 0ULL;                  // one lane per node
    int b = rowptr[node], e = rowptr[node + 1];
    float a0 = add[node * P16 + f], a1 = 0.0f, a2 = 0.0f, a3 = 0.0f;
    int i = b;
    for (; i + 4 <= e; i += 4) {
        int2 e0 = edg[i], e1 = edg[i + 1], e2 = edg[i + 2], e3 = edg[i + 3];
        float h0v = h[e0.x * P16 + f];
        float h1v = h[e1.x * P16 + f];
        float h2v = h[e2.x * P16 + f];
        float h3v = h[e3.x * P16 + f];
        a0 += __int_as_float(e0.y) * h0v;
        a1 += __int_as_float(e1.y) * h1v;
        a2 += __int_as_float(e2.y) * h2v;
        a3 += __int_as_float(e3.y) * h3v;
    }
    for (; i < e; i++) {
        int2 ev = edg[i];
        a0 += __int_as_float(ev.y) * h[ev.x * P16 + f];
    }
    float acc = (a0 + a1) + (a2 + a3);
    float mv = (f < NOUT) ? acc : -1e30f;
    #pragma unroll
    for (int o = 8; o >= 1; o >>= 1)
        mv = fmaxf(mv, __shfl_xor_sync(0xFFFFFFFFu, mv, o, 16));
    float ex = (f < NOUT) ? expf(acc - mv) : 0.0f;
    float s = ex;
    #pragma unroll
    for (int o = 8; o >= 1; o >>= 1)
        s += __shfl_xor_sync(0xFFFFFFFFu, s, o, 16);
    float l = mv + logf(s);
    if (f < NOUT) outp[node * NOUT + f] = acc - l;
}

// ---------------- fused layer GEMMs (packed f32x2 FMA) ----------------
__global__ void k_gemm_l1(const float* __restrict__ h0, const float* __restrict__ h1,
                          const float* __restrict__ h2, const float* __restrict__ h3,
                          const float* __restrict__ W, const float* __restrict__ bias,
                          float* __restrict__ outp) {
    __shared__ alignas(16) float sW[NK * FIN * HID];
    __shared__ alignas(16) float sb[HID];
    for (int i = threadIdx.x; i < NK * FIN * HID; i += blockDim.x) sW[i] = W[i];
    if (threadIdx.x < HID) sb[threadIdx.x] = bias[threadIdx.x];
    __syncthreads();

    int row = blockIdx.x * blockDim.x + threadIdx.x;
    if (row >= NN) return;
    const float* hs[NK] = {h0 + row * FIN, h1 + row * FIN, h2 + row * FIN, h3 + row * FIN};

    ull acc2[HID / 2];
    const ull* sb64 = (const ull*)sb;
    #pragma unroll
    for (int c = 0; c < HID / 2; c++) acc2[c] = sb64[c];

    #pragma unroll
    for (int kk = 0; kk < NK; kk++) {
        const float4* hp = (const float4*)hs[kk];
        float4 h04 = hp[0], h14 = hp[1];
        float hv[FIN] = {h04.x, h04.y, h04.z, h04.w, h14.x, h14.y, h14.z, h14.w};
        #pragma unroll
        for (int k = 0; k < FIN; k++) {
            ull hd = dup2(hv[k]);
            const ulonglong2* w2 = (const ulonglong2*)(sW + (kk * FIN + k) * HID);
            #pragma unroll
            for (int c = 0; c < HID / 4; c++) {
                ulonglong2 wp = w2[c];
                fma2(acc2[2 * c], wp.x, hd);
                fma2(acc2[2 * c + 1], wp.y, hd);
            }
        }
    }
    float4* op = (float4*)(outp + row * HID);
    #pragma unroll
    for (int c = 0; c < HID / 4; c++) {
        float2 u0 = unpack2(acc2[2 * c]), u1 = unpack2(acc2[2 * c + 1]);
        op[c] = make_float4(fmaxf(u0.x, 0.f), fmaxf(u0.y, 0.f),
                            fmaxf(u1.x, 0.f), fmaxf(u1.y, 0.f));
    }
}

__global__ void k_gemm_l2(const float* __restrict__ h0, const float* __restrict__ h1,
                          const float* __restrict__ h2, const float* __restrict__ h3,
                          const float* __restrict__ W, const float* __restrict__ bias,
                          float* __restrict__ outp) {
    extern __shared__ float sW[];          // 64KB
    __shared__ alignas(16) float sb[HID];
    for (int i = threadIdx.x; i < NK * HID * HID; i += blockDim.x) sW[i] = W[i];
    if (threadIdx.x < HID) sb[threadIdx.x] = bias[threadIdx.x];
    __syncthreads();

    int row = blockIdx.x * blockDim.x + threadIdx.x;
    if (row >= NN) return;
    const float* hs[NK] = {h0 + row * HID, h1 + row * HID, h2 + row * HID, h3 + row * HID};

    ull acc2[HID / 2];
    const ull* sb64 = (const ull*)sb;
    #pragma unroll
    for (int c = 0; c < HID / 2; c++) acc2[c] = sb64[c];

    for (int kk = 0; kk < NK; kk++) {
        const float4* hp = (const float4*)hs[kk];
        #pragma unroll 4
        for (int k4 = 0; k4 < HID / 4; k4++) {
            float4 hv = hp[k4];
            float hvv[4] = {hv.x, hv.y, hv.z, hv.w};
            #pragma unroll
            for (int j = 0; j < 4; j++) {
                ull hd = dup2(hvv[j]);
                const ulonglong2* w2 =
                    (const ulonglong2*)(sW + (kk * HID + k4 * 4 + j) * HID);
                #pragma unroll
                for (int c = 0; c < HID / 4; c++) {
                    ulonglong2 wp = w2[c];
                    fma2(acc2[2 * c], wp.x, hd);
                    fma2(acc2[2 * c + 1], wp.y, hd);
                }
            }
        }
    }
    float4* op = (float4*)(outp + row * HID);
    #pragma unroll
    for (int c = 0; c < HID / 4; c++) {
        float2 u0 = unpack2(acc2[2 * c]), u1 = unpack2(acc2[2 * c + 1]);
        op[c] = make_float4(fmaxf(u0.x, 0.f), fmaxf(u0.y, 0.f),
                            fmaxf(u1.x, 0.f), fmaxf(u1.y, 0.f));
    }
}

// layer-3 transforms: g_k = h @ W3[k] (bias folded into g0); pad to 16
__global__ void k_tx3(const float* __restrict__ h, const float* __restrict__ W,
                      const float* __restrict__ bias,
                      float* __restrict__ g0, float* __restrict__ g1,
                      float* __restrict__ g2, float* __restrict__ g3) {
    __shared__ float sW[NK * HID * NOUT];
    __shared__ float sb[NOUT];
    for (int i = threadIdx.x; i < NK * HID * NOUT; i += blockDim.x) sW[i] = W[i];
    if (threadIdx.x < NOUT) sb[threadIdx.x] = bias[threadIdx.x];
    __syncthreads();

    int row = blockIdx.x * blockDim.x + threadIdx.x;
    if (row >= NN) return;
    const float4* hp = (const float4*)(h + row * HID);

    float acc[NK * NOUT];
    #pragma unroll
    for (int kk = 0; kk < NK; kk++)
        #pragma unroll
        for (int c = 0; c < NOUT; c++)
            acc[kk * NOUT + c] = (kk == 0) ? sb[c] : 0.0f;

    for (int k4 = 0; k4 < HID / 4; k4++) {
        float4 hv = hp[k4];
        #pragma unroll
        for (int kk = 0; kk < NK; kk++) {
            const float* w = sW + kk * HID * NOUT + (k4 * 4) * NOUT;
            #pragma unroll
            for (int c = 0; c < NOUT; c++) acc[kk * NOUT + c] += hv.x * w[c];
            #pragma unroll
            for (int c = 0; c < NOUT; c++) acc[kk * NOUT + c] += hv.y * w[NOUT + c];
            #pragma unroll
            for (int c = 0; c < NOUT; c++) acc[kk * NOUT + c] += hv.z * w[2 * NOUT + c];
            #pragma unroll
            for (int c = 0; c < NOUT; c++) acc[kk * NOUT + c] += hv.w * w[3 * NOUT + c];
        }
    }
    float* gs[NK] = {g0 + row * P16, g1 + row * P16, g2 + row * P16, g3 + row * P16};
    #pragma unroll
    for (int kk = 0; kk < NK; kk++) {
        #pragma unroll
        for (int c = 0; c < NOUT; c++) gs[kk][c] = acc[kk * NOUT + c];
        #pragma unroll
        for (int c = NOUT; c < P16; c++) gs[kk][c] = 0.0f;
    }
}

// ---------------- launch ----------------
extern "C" void kernel_launch(void* const* d_in, const int* in_sizes, int n_in,
                              void* d_out, int out_size) {
    const float *x = 0, *pos = 0, *ea = 0, *W1 = 0, *b1 = 0, *W2 = 0, *b2 = 0,
                *W3 = 0, *b3 = 0;
    const int* ei32 = 0;
    for (int i = 0; i < n_in; i++) {
        switch (in_sizes[i]) {
            case 1600000: ei32 = (const int*)d_in[i]; break;
            case  800000: ea  = (const float*)d_in[i]; break;
            case  300000: x   = (const float*)d_in[i]; break;
            case  100000: pos = (const float*)d_in[i]; break;
            case    2048: W1  = (const float*)d_in[i]; break;
            case   16384: W2  = (const float*)d_in[i]; break;
            case    2560: W3  = (const float*)d_in[i]; break;
            case      10: b3  = (const float*)d_in[i]; break;
            case      64:
                if (!b1) b1 = (const float*)d_in[i];
                else     b2 = (const float*)d_in[i];
                break;
            default: break;
        }
    }
    float* out = (float*)d_out;

    Scratch* S;
    cudaGetSymbolAddress((void**)&S, g_s);
    cudaFuncSetAttribute(k_gemm_l2, cudaFuncAttributeMaxDynamicSharedMemorySize,
                         NK * HID * HID * (int)sizeof(float));

    const int BE = (NE + 255) / 256;
    const int BG = (NN + 127) / 128;
    const int BG2 = (NN + 255) / 256;
    const int BW = (NN + 7) / 8;
    const int B8  = (NN + 31) / 32;
    const int B16 = (NN + 15) / 16;

    k_deg_cnt<<<BE, 256>>>(ei32, ea, x, pos, S->h0, S->pk);
    k_scan<<<NSCANB, 256>>>((const ull*)S->pk, S->rowptr, S->cursor, S->dinv, S->bsum);
    k_fill<<<BE, 256>>>(ei32, ea, (const float*)S->dinv, S->cursor, S->edg);

    // layer 1 (F=8 -> 64)
    k_propW<8><<<B8, 256>>>(S->h0,  nullptr, S->t8a, S->rowptr, S->edg);
    k_propW<8><<<B8, 256>>>(S->t8a, nullptr, S->t8b, S->rowptr, S->edg);
    k_propW<8><<<B8, 256>>>(S->t8b, nullptr, S->t8c, S->rowptr, S->edg);
    k_gemm_l1<<<BG, 128>>>(S->h0, S->t8a, S->t8b, S->t8c, W1, b1, S->hA);

    // layer 2 hops (fp32, 4-deep pipelined gathers, exact-size grids)
    k_prop64<<<BW, 256>>>((const ull*)S->hA, (ull*)S->hB, S->rowptr, S->edg);
    k_prop64<<<BW, 256>>>((const ull*)S->hB, (ull*)S->hC, S->rowptr, S->edg);
    k_prop64<<<BW, 256>>>((const ull*)S->hC, (ull*)S->hD, S->rowptr, S->edg);
    k_gemm_l2<<<BG2, 256, NK * HID * HID * (int)sizeof(float)>>>(
        S->hA, S->hB, S->hC, S->hD, W2, b2, S->hA);

    // layer 3 (64 -> 10): transform first, then Horner propagate at width 16
    k_tx3<<<BG, 128>>>(S->hA, W3, b3, S->g0, S->g1, S->g2, S->g3);
    k_propW<16><<<B16, 256>>>(S->g3,  S->g2, S->p16a, S->rowptr, S->edg);
    k_propW<16><<<B16, 256>>>(S->p16a, S->g1, S->p16b, S->rowptr, S->edg);
    k_prop16_lsm<<<B16, 256>>>(S->p16b, S->g0, out, S->rowptr, S->edg,
                               S->pk, S->bsum);
}